// round 13
// baseline (speedup 1.0000x reference)
#include <cuda_runtime.h>
#include <cuda_bf16.h>

#define PI_F 3.14159265358979323846f
#define SQ2H 0.70710678118654752440f

// ---------------------------------------------------------------------------
// Static device scratch (runtime allocation is forbidden)
// ---------------------------------------------------------------------------
// State S[b][x][y][f]: 512*128*128*2 complex64 = 134 MB (16B-aligned for float4)
__device__ __align__(16) float2 g_S[16777216];
// Partial probabilities P2[b][x][ya*2+f]: 512*128*64 floats
__device__ float  g_P2[4194304];
// Precomputed mux unitaries (cr, ax*sn, ay*sn, az*sn)
//   [0,16384):     mux0 idx = x*128 + y
//   [16384,32768): mux1 idx = ((cx*2+cy)*64 + xa)*64 + ya
//   [32768,36864): mux2 idx = ((cx*2+cy)*32 + xa)*32 + ya
__device__ float4 g_U[36864];

__device__ __forceinline__ float2 cmulf(float2 a, float2 b) {
    return make_float2(a.x * b.x - a.y * b.y, a.x * b.y + a.y * b.x);
}
__device__ __forceinline__ float2 cadd(float2 a, float2 b) { return make_float2(a.x + b.x, a.y + b.y); }
__device__ __forceinline__ float2 csub(float2 a, float2 b) { return make_float2(a.x - b.x, a.y - b.y); }

template<bool INV>
__device__ __forceinline__ float2 mul_j(float2 t) {   // fwd: -i*t ; inv: +i*t
    return INV ? make_float2(-t.y, t.x) : make_float2(t.y, -t.x);
}
template<bool INV>
__device__ __forceinline__ float2 twget(const float2* tw, int idx) {
    float2 w = tw[idx];
    if (INV) w.y = -w.y;
    return w;
}

// DFT-8 butterfly, registers only.
template<bool INV>
__device__ __forceinline__ void bfly8(const float2 a[8], float2 y[8])
{
    float2 t0 = cadd(a[0], a[4]), t1 = csub(a[0], a[4]);
    float2 t2 = cadd(a[2], a[6]), t3 = csub(a[2], a[6]);
    float2 jt3 = mul_j<INV>(t3);
    float2 E0 = cadd(t0, t2), E1 = cadd(t1, jt3), E2 = csub(t0, t2), E3 = csub(t1, jt3);
    float2 s0 = cadd(a[1], a[5]), s1 = csub(a[1], a[5]);
    float2 s2 = cadd(a[3], a[7]), s3 = csub(a[3], a[7]);
    float2 js3 = mul_j<INV>(s3);
    float2 O0 = cadd(s0, s2), O1 = cadd(s1, js3), O2 = csub(s0, s2), O3 = csub(s1, js3);
    float2 O1p, O2p, O3p;
    if (!INV) {
        O1p = make_float2(SQ2H * (O1.x + O1.y),  SQ2H * (O1.y - O1.x));
        O2p = make_float2(O2.y, -O2.x);
        O3p = make_float2(-SQ2H * (O3.x - O3.y), -SQ2H * (O3.x + O3.y));
    } else {
        O1p = make_float2(SQ2H * (O1.x - O1.y),  SQ2H * (O1.x + O1.y));
        O2p = make_float2(-O2.y, O2.x);
        O3p = make_float2(-SQ2H * (O3.x + O3.y), -SQ2H * (O3.y - O3.x));
    }
    y[0] = cadd(E0, O0);  y[4] = csub(E0, O0);
    y[1] = cadd(E1, O1p); y[5] = csub(E1, O1p);
    y[2] = cadd(E2, O2p); y[6] = csub(E2, O2p);
    y[3] = cadd(E3, O3p); y[7] = csub(E3, O3p);
}

// ---------------------------------------------------------------------------
// CTA tile: 32 lines x 128 complexes, in-place buffer A, stride 129 float2.
// 512 threads, ONE radix-8 butterfly per thread per stage. Warp lanes sweep
// 32 consecutive logical lines (phys line = ll & 31) with a fixed column
// offset per instruction -> every smem phase hits 16 distinct banks.
// Logical line for length L: phys l = ll & 31, segment = ll >> 5.
// LOCAL=true when the thread's read and write slots coincide (no mid-sync).
// ---------------------------------------------------------------------------
template<int LG2L, int S, bool INV, bool NOTW, bool LOCAL>
__device__ __forceinline__ void stage8_ip(float2* __restrict__ A, const float2* tw,
                                          int tid, float sc)
{
    constexpr int L = 1 << LG2L;
    constexpr int NL = 4096 >> LG2L;
    constexpr int LG2NL = 12 - LG2L;
    constexpr int OFF = L / 8;
    const int ll = tid & (NL - 1);
    const int u  = tid >> LG2NL;                  // [0, L/8)
    const int base = (ll & 31) * 129 + ((ll >> 5) << LG2L);
    const int q  = u & (S - 1);
    const int ps = u - q;                         // S*p
    float2 a[8], y[8];
    #pragma unroll
    for (int j = 0; j < 8; j++) a[j] = A[base + u + j * OFF];
    bfly8<INV>(a, y);
    if (!NOTW) {
        const int e = ps << (7 - LG2L);
        #pragma unroll
        for (int k = 1; k < 8; k++) y[k] = cmulf(y[k], twget<INV>(tw, k * e));
    }
    #pragma unroll
    for (int k = 0; k < 8; k++) { y[k].x *= sc; y[k].y *= sc; }
    if (!LOCAL) __syncthreads();
    const int d0 = base + q + 8 * ps;
    #pragma unroll
    for (int k = 0; k < 8; k++) A[d0 + k * S] = y[k];
    __syncthreads();
}

// Final radix-2 stage for L=128 (s=64, trivial twiddle), thread-local pairs.
__device__ __forceinline__ void stage2_128ip(float2* __restrict__ A, int tid)
{
    constexpr float sc = 0.08838834764831845f;    // 1/sqrt(128)
    const int l  = tid & 31;
    const int u0 = tid >> 5;                      // [0,16)
    #pragma unroll
    for (int it = 0; it < 4; it++) {
        int u = u0 + 16 * it;                     // [0,64)
        int i = l * 129 + u;
        float2 a = A[i], b = A[i + 64];
        A[i]      = make_float2((a.x + b.x) * sc, (a.y + b.y) * sc);
        A[i + 64] = make_float2((a.x - b.x) * sc, (a.y - b.y) * sc);
    }
    __syncthreads();
}

// Final radix-4 stage for L=32 (s=8, trivial twiddles), thread-local slots.
template<bool INV>
__device__ __forceinline__ void stage4_32ip(float2* __restrict__ A, int tid)
{
    constexpr float sc = 0.17677669529663687f;    // 1/sqrt(32)
    #pragma unroll
    for (int it = 0; it < 2; it++) {
        int item = tid + 512 * it;
        int ll = item & 127;
        int u  = item >> 7;                       // [0,8)
        int base = (ll & 31) * 129 + ((ll >> 5) << 5);
        float2 a0 = A[base + u],      a1 = A[base + u + 8];
        float2 a2 = A[base + u + 16], a3 = A[base + u + 24];
        float2 t0 = cadd(a0, a2), t1 = csub(a0, a2);
        float2 t2 = cadd(a1, a3), t3 = csub(a1, a3);
        float2 jt = mul_j<INV>(t3);
        A[base + u]      = make_float2((t0.x + t2.x) * sc, (t0.y + t2.y) * sc);
        A[base + u + 8]  = make_float2((t1.x + jt.x) * sc, (t1.y + jt.y) * sc);
        A[base + u + 16] = make_float2((t0.x - t2.x) * sc, (t0.y - t2.y) * sc);
        A[base + u + 24] = make_float2((t1.x - jt.x) * sc, (t1.y - jt.y) * sc);
    }
    __syncthreads();
}

// Composite transforms (in-place, trailing sync included).
template<bool INV>
__device__ __forceinline__ void fft128(float2* A, const float2* tw, int tid) {
    stage8_ip<7, 1, INV, false, false>(A, tw, tid, 1.0f);
    stage8_ip<7, 8, INV, false, false>(A, tw, tid, 1.0f);
    stage2_128ip(A, tid);
}
template<bool INV>
__device__ __forceinline__ void fft64(float2* A, const float2* tw, int tid) {
    stage8_ip<6, 1, INV, false, false>(A, tw, tid, 1.0f);
    stage8_ip<6, 8, INV, true,  true >(A, tw, tid, 0.125f);   // p==0: no twiddle, local
}
template<bool INV>
__device__ __forceinline__ void fft32(float2* A, const float2* tw, int tid) {
    stage8_ip<5, 1, INV, false, false>(A, tw, tid, 1.0f);
    stage4_32ip<INV>(A, tid);
}

// exp(-i a.sigma) on the feature pair, q = (cr, ax*sn, ay*sn, az*sn)
__device__ __forceinline__ void mux_apply(float4 q, float2& p0, float2& p1)
{
    float cr = q.x, sx = q.y, sy = q.z, sz = q.w;
    float2 n0 = make_float2(cr * p0.x + sz * p0.y - sy * p1.x + sx * p1.y,
                            cr * p0.y - sz * p0.x - sy * p1.y - sx * p1.x);
    float2 n1 = make_float2(sy * p0.x + sx * p0.y + cr * p1.x - sz * p1.y,
                            sy * p0.y - sx * p0.x + cr * p1.y + sz * p1.x);
    p0 = n0; p1 = n1;
}

#define DECL_SMEM                                                             \
    __shared__ float2 A[32 * 129];                                            \
    __shared__ float2 tw[128];                                                \
    const int tid = threadIdx.x;                                              \
    if (tid < 128) {                                                          \
        float sn, cs;                                                         \
        __sincosf(-2.0f * PI_F * (float)tid * (1.0f / 128.0f), &sn, &cs);     \
        tw[tid] = make_float2(cs, sn);                                        \
    }

// Row-pass line layout: phys line l = r + 16f (r = local x-row in [0,16)).
// Col-pass line layout: phys line l = yl + 16f (yl = local y in [0,16)).

// ---- K0: precompute the 36864 mux unitaries --------------------------------
__global__ void __launch_bounds__(256) k0_prep(const float* __restrict__ mux0,
                                               const float* __restrict__ mux1,
                                               const float* __restrict__ mux2)
{
    int i = blockIdx.x * 256 + threadIdx.x;
    if (i >= 36864) return;
    const float* src;
    if (i < 16384)      src = mux0 + (size_t)i * 3;
    else if (i < 32768) src = mux1 + (size_t)(i - 16384) * 3;
    else                src = mux2 + (size_t)(i - 32768) * 3;
    float ax = src[0], ay = src[1], az = src[2];
    float r = sqrtf(ax * ax + ay * ay + az * az + 1e-20f);
    float sr, cr;
    sincosf(r, &sr, &cr);
    float sn = sr / r;
    g_U[i] = make_float4(cr, ax * sn, ay * sn, az * sn);
}

// ---- K1: FRQI encode + FFTy(128). 16 (b,x)-rows per CTA --------------------
__global__ void __launch_bounds__(512, 2) k1_row(const float* __restrict__ images)
{
    DECL_SMEM
    int bi = blockIdx.x >> 3;
    int x0 = (blockIdx.x & 7) << 4;
    const float* img = images + (size_t)(bi * 128 + x0) * 128;
    #pragma unroll
    for (int it = 0; it < 4; it++) {
        int e = tid + 512 * it;                 // [0,2048)
        int r = e >> 7, y = e & 127;
        float v = img[r * 128 + y];
        float sn, cs;
        __sincosf(0.5f * PI_F * v, &sn, &cs);
        A[r * 129 + y]        = make_float2(cs * (1.0f / 128.0f), 0.0f);
        A[(r + 16) * 129 + y] = make_float2(sn * (1.0f / 128.0f), 0.0f);
    }
    __syncthreads();
    fft128<false>(A, tw, tid);
    float4* S4 = reinterpret_cast<float4*>(g_S) + (size_t)(bi * 128 + x0) * 128;
    #pragma unroll
    for (int it = 0; it < 4; it++) {
        int e = tid + 512 * it;
        int r = e >> 7, y = e & 127;
        float2 f0 = A[r * 129 + y];
        float2 f1 = A[(r + 16) * 129 + y];
        S4[r * 128 + y] = make_float4(f0.x, f0.y, f1.x, f1.y);
    }
}

// ---- K2: FFTx128 . mux0 . IFFTx128 . FFTx64. 16 y per CTA ------------------
__global__ void __launch_bounds__(512, 2) k2_col()
{
    DECL_SMEM
    int bi = blockIdx.x >> 3;
    int y0 = (blockIdx.x & 7) << 4;
    float4* S4 = reinterpret_cast<float4*>(g_S) + (size_t)bi * 16384 + y0;
    #pragma unroll
    for (int it = 0; it < 4; it++) {
        int e = tid + 512 * it;                 // [0,2048)
        int x = e >> 4, yl = e & 15;
        float4 v = S4[x * 128 + yl];
        A[yl * 129 + x]        = make_float2(v.x, v.y);
        A[(yl + 16) * 129 + x] = make_float2(v.z, v.w);
    }
    __syncthreads();
    fft128<false>(A, tw, tid);
    #pragma unroll
    for (int it = 0; it < 4; it++) {
        int w = tid + 512 * it;
        int x = w >> 4, yl = w & 15;
        float4 q = g_U[x * 128 + y0 + yl];
        float2 p0 = A[yl * 129 + x];
        float2 p1 = A[(yl + 16) * 129 + x];
        mux_apply(q, p0, p1);
        A[yl * 129 + x]        = p0;
        A[(yl + 16) * 129 + x] = p1;
    }
    __syncthreads();
    fft128<true>(A, tw, tid);
    fft64<false>(A, tw, tid);
    #pragma unroll
    for (int it = 0; it < 4; it++) {
        int e = tid + 512 * it;
        int x = e >> 4, yl = e & 15;
        float2 f0 = A[yl * 129 + x];
        float2 f1 = A[(yl + 16) * 129 + x];
        S4[x * 128 + yl] = make_float4(f0.x, f0.y, f1.x, f1.y);
    }
}

// ---- K3: IFFTy128 . FFTy64 . mux1 . IFFTy64 . FFTy32. 16 rows per CTA ------
__global__ void __launch_bounds__(512, 2) k3_row()
{
    DECL_SMEM
    int bi = blockIdx.x >> 3;
    int x0 = (blockIdx.x & 7) << 4;
    float4* S4 = reinterpret_cast<float4*>(g_S) + (size_t)(bi * 128 + x0) * 128;
    #pragma unroll
    for (int it = 0; it < 4; it++) {
        int e = tid + 512 * it;
        int r = e >> 7, y = e & 127;
        float4 v = S4[r * 128 + y];
        A[r * 129 + y]        = make_float2(v.x, v.y);
        A[(r + 16) * 129 + y] = make_float2(v.z, v.w);
    }
    __syncthreads();
    fft128<true>(A, tw, tid);
    fft64<false>(A, tw, tid);
    #pragma unroll
    for (int it = 0; it < 4; it++) {
        int w = tid + 512 * it;
        int r = w >> 7, y = w & 127;
        int x = x0 + r;
        int cx = x >> 6, xa = x & 63;
        int cy = y >> 6, ya = y & 63;
        float4 q = g_U[16384 + ((cx * 2 + cy) * 64 + xa) * 64 + ya];
        float2 p0 = A[r * 129 + y];
        float2 p1 = A[(r + 16) * 129 + y];
        mux_apply(q, p0, p1);
        A[r * 129 + y]        = p0;
        A[(r + 16) * 129 + y] = p1;
    }
    __syncthreads();
    fft64<true>(A, tw, tid);
    fft32<false>(A, tw, tid);
    #pragma unroll
    for (int it = 0; it < 4; it++) {
        int e = tid + 512 * it;
        int r = e >> 7, y = e & 127;
        float2 f0 = A[r * 129 + y];
        float2 f1 = A[(r + 16) * 129 + y];
        S4[r * 128 + y] = make_float4(f0.x, f0.y, f1.x, f1.y);
    }
}

// ---- K4: IFFTx64 . FFTx32 . mux2 . IFFTx32. 16 y per CTA -------------------
__global__ void __launch_bounds__(512, 2) k4_col()
{
    DECL_SMEM
    int bi = blockIdx.x >> 3;
    int y0 = (blockIdx.x & 7) << 4;
    float4* S4 = reinterpret_cast<float4*>(g_S) + (size_t)bi * 16384 + y0;
    #pragma unroll
    for (int it = 0; it < 4; it++) {
        int e = tid + 512 * it;
        int x = e >> 4, yl = e & 15;
        float4 v = S4[x * 128 + yl];
        A[yl * 129 + x]        = make_float2(v.x, v.y);
        A[(yl + 16) * 129 + x] = make_float2(v.z, v.w);
    }
    __syncthreads();
    fft64<true>(A, tw, tid);
    fft32<false>(A, tw, tid);
    #pragma unroll
    for (int it = 0; it < 4; it++) {
        int w = tid + 512 * it;
        int x = w >> 4, yl = w & 15;
        int y = y0 + yl;
        int cx = (x >> 5) & 1, xa = x & 31;
        int cy = (y >> 5) & 1, ya = y & 31;
        float4 q = g_U[32768 + ((cx * 2 + cy) * 32 + xa) * 32 + ya];
        float2 p0 = A[yl * 129 + x];
        float2 p1 = A[(yl + 16) * 129 + x];
        mux_apply(q, p0, p1);
        A[yl * 129 + x]        = p0;
        A[(yl + 16) * 129 + x] = p1;
    }
    __syncthreads();
    fft32<true>(A, tw, tid);
    #pragma unroll
    for (int it = 0; it < 4; it++) {
        int e = tid + 512 * it;
        int x = e >> 4, yl = e & 15;
        float2 f0 = A[yl * 129 + x];
        float2 f1 = A[(yl + 16) * 129 + x];
        S4[x * 128 + yl] = make_float4(f0.x, f0.y, f1.x, f1.y);
    }
}

// ---- K5: IFFTy32 + measure (sum over yc). 16 rows per CTA ------------------
__global__ void __launch_bounds__(512, 2) k5_row()
{
    DECL_SMEM
    int bi = blockIdx.x >> 3;
    int x0 = (blockIdx.x & 7) << 4;
    float4* S4 = reinterpret_cast<float4*>(g_S) + (size_t)(bi * 128 + x0) * 128;
    #pragma unroll
    for (int it = 0; it < 4; it++) {
        int e = tid + 512 * it;
        int r = e >> 7, y = e & 127;
        float4 v = S4[r * 128 + y];
        A[r * 129 + y]        = make_float2(v.x, v.y);
        A[(r + 16) * 129 + y] = make_float2(v.z, v.w);
    }
    __syncthreads();
    fft32<true>(A, tw, tid);
    #pragma unroll
    for (int it = 0; it < 2; it++) {
        int w = tid + 512 * it;                 // [0,1024)
        int r = w >> 6, f = (w >> 5) & 1, ya = w & 31;
        const float2* line = A + (r + 16 * f) * 129;
        float sum = 0.0f;
        #pragma unroll
        for (int g = 0; g < 4; g++) {
            float2 v = line[g * 32 + ya];
            sum += v.x * v.x + v.y * v.y;
        }
        g_P2[(size_t)bi * 8192 + (x0 + r) * 64 + ya * 2 + f] = sum;
    }
}

// ---- K6: reduce over xc + [1,2048]x[2048,10] GEMM + bias -------------------
__global__ void __launch_bounds__(256) k6_gemm(const float* __restrict__ W,
                                               const float* __restrict__ bias,
                                               float* __restrict__ out)
{
    __shared__ float acc[2048];
    __shared__ float red[8][10];
    const int tid = threadIdx.x;
    const int bi = blockIdx.x;
    const float* P = g_P2 + (size_t)bi * 8192;   // [x][ya*2+f] = [128][64]
    for (int j = tid; j < 2048; j += 256) {
        int xa = j >> 6, t = j & 63;
        acc[j] = P[xa * 64 + t] + P[(32 + xa) * 64 + t]
               + P[(64 + xa) * 64 + t] + P[(96 + xa) * 64 + t];
    }
    __syncthreads();
    float part[10];
    #pragma unroll
    for (int c = 0; c < 10; c++) part[c] = 0.0f;
    for (int j = tid; j < 2048; j += 256) {
        float v = acc[j];
        #pragma unroll
        for (int c = 0; c < 10; c++) part[c] += v * W[c * 2048 + j];
    }
    #pragma unroll
    for (int o = 16; o > 0; o >>= 1) {
        #pragma unroll
        for (int c = 0; c < 10; c++)
            part[c] += __shfl_xor_sync(0xffffffffu, part[c], o);
    }
    if ((tid & 31) == 0) {
        int wi = tid >> 5;
        #pragma unroll
        for (int c = 0; c < 10; c++) red[wi][c] = part[c];
    }
    __syncthreads();
    if (tid < 10) {
        float s = bias[tid];
        #pragma unroll
        for (int wi = 0; wi < 8; wi++) s += red[wi][tid];
        out[bi * 10 + tid] = s;
    }
}

// ---------------------------------------------------------------------------
extern "C" void kernel_launch(void* const* d_in, const int* in_sizes, int n_in,
                              void* d_out, int out_size)
{
    const float* images = (const float*)d_in[0];
    const float* mux0   = (const float*)d_in[1];
    const float* mux1   = (const float*)d_in[2];
    const float* mux2   = (const float*)d_in[3];
    const float* W      = (const float*)d_in[4];
    const float* bias   = (const float*)d_in[5];
    float* out = (float*)d_out;

    k0_prep<<<144, 256>>>(mux0, mux1, mux2);
    k1_row<<<4096, 512>>>(images);
    k2_col<<<4096, 512>>>();
    k3_row<<<4096, 512>>>();
    k4_col<<<4096, 512>>>();
    k5_row<<<4096, 512>>>();
    k6_gemm<<<512, 256>>>(W, bias, out);
}